// round 16
// baseline (speedup 1.0000x reference)
#include <cuda_runtime.h>
#include <cuda_fp16.h>

#define NN 100000
#define NE 3200000
#define NF 128
#define NH 16
#define MH 100
#define NC 12
#define NG 512
#define NBLK 391        // ceil(NN/256)
#define FILL4BLK 3125   // NE / (256*4)
#define CSRCAP (NE + 3 * NN)   // rowstarts padded to multiples of 4

// ---- device scratch (static, no allocation; 16B-aligned).
// g_deg / g_pooled: zero-init by CUDA, re-zeroed by last reader per launch.
__device__ __align__(16) int            g_csr[CSRCAP];   // src index only
__device__ __align__(16) unsigned short g_pos[NE];       // within-row slot of each edge
__device__ __align__(16) int    g_deg[NN];
__device__ __align__(16) int    g_rowstart[NN];
__device__ __align__(16) int    g_blocksum[512];
__device__ __align__(16) float  g_dinv[NN];
__device__ __align__(16) float  g_hpre[NN * NH];    // x @ W1 (unscaled fp32)
__device__ __align__(16) __half g_hpreh[NN * NH];   // fp16: dinv * (x @ W1)
__device__ __align__(16) __half g_hpre2h[NN * NH];  // fp16: dinv * (h1 @ W2)
__device__ __align__(16) float  g_pooled[NG * NH];

__device__ __forceinline__ void red4(float* p, float4 v) {
    asm volatile("red.global.add.v4.f32 [%0], {%1,%2,%3,%4};"
                 :: "l"(p), "f"(v.x), "f"(v.y), "f"(v.z), "f"(v.w)
                 : "memory");
}
__device__ __forceinline__ float4 fma4(float s, float4 a, float4 acc) {
    acc.x = fmaf(s, a.x, acc.x); acc.y = fmaf(s, a.y, acc.y);
    acc.z = fmaf(s, a.z, acc.z); acc.w = fmaf(s, a.w, acc.w);
    return acc;
}
__device__ __forceinline__ float4 add4(float4 a, float4 b) {
    a.x += b.x; a.y += b.y; a.z += b.z; a.w += b.w; return a;
}
// 8-byte gather of 4 fp16 features -> float4
__device__ __forceinline__ float4 ldh4(const __half* __restrict__ base, int node, int f4) {
    uint2 u = __ldg((const uint2*)(base + node * NH + f4 * 4));
    __half2 a = *(__half2*)&u.x;
    __half2 b = *(__half2*)&u.y;
    float2 fa = __half22float2(a);
    float2 fb = __half22float2(b);
    return make_float4(fa.x, fa.y, fb.x, fb.y);
}
// store float4 as 4 fp16 (8 bytes)
__device__ __forceinline__ void sth4(__half* __restrict__ base, int node, int f4, float4 v) {
    uint2 u;
    __half2 a = __floats2half2_rn(v.x, v.y);
    __half2 b = __floats2half2_rn(v.z, v.w);
    u.x = *(unsigned*)&a;
    u.y = *(unsigned*)&b;
    *(uint2*)(base + node * NH + f4 * 4) = u;
}
// int64 buffers viewed as int32 are [v,0,v,0,...]; sample odd words of the
// EDGE INDEX ONLY (batch_vec is sorted -> leading zeros legitimate there).
__device__ __forceinline__ int probe64(const int* p32) {
    int nz = 0;
#pragma unroll
    for (int k = 1; k < 16; k += 2) nz |= p32[k];
    return nz == 0;
}
// load 4 consecutive edge indices at position e (e % 4 == 0)
__device__ __forceinline__ int4 ld4idx(const void* col, int e, int is64) {
    if (is64) {
        ulonglong2 a = __ldg((const ulonglong2*)((const long long*)col + e));
        ulonglong2 b = __ldg((const ulonglong2*)((const long long*)col + e) + 1);
        return make_int4((int)a.x, (int)a.y, (int)b.x, (int)b.y);
    }
    return __ldg((const int4*)((const int*)col + e));
}

// ---- degree count + per-edge slot record, 4 edges/thread, high occupancy ----
__global__ __launch_bounds__(256) void k_deg(const void* __restrict__ ei) {
    __shared__ int is64s;
    if (threadIdx.x == 0) is64s = probe64((const int*)ei);
    __syncthreads();
    int e = (blockIdx.x * 256 + threadIdx.x) * 4;
    if (e >= NE) return;
    const void* dstcol = is64s ? (const void*)((const long long*)ei + NE)
                               : (const void*)((const int*)ei + NE);
    int4 d = ld4idx(dstcol, e, is64s);
    ushort4 p;
    p.x = (unsigned short)atomicAdd(&g_deg[d.x], 1);
    p.y = (unsigned short)atomicAdd(&g_deg[d.y], 1);
    p.z = (unsigned short)atomicAdd(&g_deg[d.z], 1);
    p.w = (unsigned short)atomicAdd(&g_deg[d.w], 1);
    *(ushort4*)(g_pos + e) = p;
}

// ---- scanA (blocks [0,NBLK)) + gemm1 unscaled fp32 (blocks [NBLK, 2*NBLK)) ----
__global__ __launch_bounds__(256) void k_scanAgemm(const float* __restrict__ x,
                                                   const float* __restrict__ W1) {
    if (blockIdx.x < NBLK) {
        __shared__ int s[256];
        int i = blockIdx.x * 256 + threadIdx.x;
        s[threadIdx.x] = (i < NN) ? ((g_deg[i] + 3) & ~3) : 0;
        __syncthreads();
        for (int o = 128; o > 0; o >>= 1) {
            if (threadIdx.x < o) s[threadIdx.x] += s[threadIdx.x + o];
            __syncthreads();
        }
        if (threadIdx.x == 0) g_blocksum[blockIdx.x] = s[0];
        return;
    }
    __shared__ float4 w4[NF * 4];   // w4[k*4+q] = W1[k][4q..4q+3]
    for (int i = threadIdx.x; i < NF * 4; i += blockDim.x)
        w4[i] = ((const float4*)W1)[i];
    __syncthreads();
    int r = (blockIdx.x - NBLK) * 256 + threadIdx.x;
    if (r >= NN) return;
    float4 a0 = make_float4(0.f, 0.f, 0.f, 0.f);
    float4 a1 = a0, a2 = a0, a3 = a0;
    const float4* xr = (const float4*)(x + (size_t)r * NF);
#pragma unroll 4
    for (int k4 = 0; k4 < NF / 4; k4++) {
        float4 xv = __ldg(xr + k4);
        const float4* wr = &w4[(4 * k4) * 4];
        a0 = fma4(xv.x, wr[0], a0); a1 = fma4(xv.x, wr[1], a1);
        a2 = fma4(xv.x, wr[2], a2); a3 = fma4(xv.x, wr[3], a3);
        a0 = fma4(xv.y, wr[4], a0); a1 = fma4(xv.y, wr[5], a1);
        a2 = fma4(xv.y, wr[6], a2); a3 = fma4(xv.y, wr[7], a3);
        a0 = fma4(xv.z, wr[8], a0); a1 = fma4(xv.z, wr[9], a1);
        a2 = fma4(xv.z, wr[10], a2); a3 = fma4(xv.z, wr[11], a3);
        a0 = fma4(xv.w, wr[12], a0); a1 = fma4(xv.w, wr[13], a1);
        a2 = fma4(xv.w, wr[14], a2); a3 = fma4(xv.w, wr[15], a3);
    }
    float4* o = (float4*)(g_hpre + (size_t)r * NH);
    o[0] = a0; o[1] = a1; o[2] = a2; o[3] = a3;
}

// ---- scanB: block-offset reduction + local scan -> rowstart/dinv;
//      convert hpre fp32 -> scaled fp16 hpreh ----
__global__ void k_scanB() {
    __shared__ int s[256];
    __shared__ int off;
    int t = threadIdx.x;
    int b = blockIdx.x;
    int v = 0;
    if (t < b) v = g_blocksum[t];
    if (t + 256 < b) v += g_blocksum[t + 256];
    s[t] = v;
    __syncthreads();
    for (int o = 128; o > 0; o >>= 1) {
        if (t < o) s[t] += s[t + o];
        __syncthreads();
    }
    if (t == 0) off = s[0];
    __syncthreads();
    int i = b * 256 + t;
    int d  = (i < NN) ? g_deg[i] : 0;
    int d4 = (d + 3) & ~3;
    s[t] = d4;
    __syncthreads();
    for (int o = 1; o < 256; o <<= 1) {
        int vv = (t >= o) ? s[t - o] : 0;
        __syncthreads();
        s[t] += vv;
        __syncthreads();
    }
    if (i < NN) {
        g_rowstart[i] = off + s[t] - d4;
        float di = rsqrtf((float)(d + 1));
        g_dinv[i] = di;
        const float4* hp = (const float4*)(g_hpre + (size_t)i * NH);
        float4 z = make_float4(0.f, 0.f, 0.f, 0.f);
#pragma unroll
        for (int q = 0; q < 4; q++)
            sth4(g_hpreh, i, q, fma4(di, hp[q], z));
    }
}

// ---- CSR fill, standalone, atomic-free, 4 edges/thread, high occupancy ----
__global__ __launch_bounds__(256) void k_fill(const void* __restrict__ ei) {
    __shared__ int is64s;
    if (threadIdx.x == 0) is64s = probe64((const int*)ei);
    __syncthreads();
    int e = (blockIdx.x * 256 + threadIdx.x) * 4;
    if (e >= NE) return;
    const void* dstcol = is64s ? (const void*)((const long long*)ei + NE)
                               : (const void*)((const int*)ei + NE);
    int4 s = ld4idx(ei, e, is64s);
    int4 d = ld4idx(dstcol, e, is64s);
    ushort4 p = *(const ushort4*)(g_pos + e);
    g_csr[__ldg(&g_rowstart[d.x]) + p.x] = s.x;
    g_csr[__ldg(&g_rowstart[d.y]) + p.y] = s.y;
    g_csr[__ldg(&g_rowstart[d.z]) + p.z] = s.z;
    g_csr[__ldg(&g_rowstart[d.w]) + p.w] = s.w;
}

// ---- fused agg+fin, 4 threads per dst (f4 = 4-feature chunk), fp16 gathers ----
// out_pre[d] = dinv[d] * (sum_{s in N(d)} hs[s] + hs[d])
// LAYER 1: h = relu(out_pre + b1); hpre2h = dinv[d] * (h @ W2)  (shuffle-based)
// LAYER 2: v = relu(out_pre + b2); pool via red4; re-zero g_deg
template <int LAYER>
__global__ __launch_bounds__(256) void k_aggfin(const float* __restrict__ bias,
                                                const float* __restrict__ W2,
                                                const void* __restrict__ batch,
                                                const void* __restrict__ ei) {
    __shared__ float4 w2s4[NH * 4];   // [j*4+q] = W2[j][4q..4q+3]
    __shared__ float bs[NH];
    __shared__ int is64s;
    if (LAYER == 1 && threadIdx.x < NH * 4) w2s4[threadIdx.x] = ((const float4*)W2)[threadIdx.x];
    if (threadIdx.x < NH) bs[threadIdx.x] = bias[threadIdx.x];
    if (LAYER == 2 && threadIdx.x == 0) is64s = probe64((const int*)ei);  // probe EI, not batch
    __syncthreads();

    int tid = blockIdx.x * blockDim.x + threadIdx.x;
    int dst = tid >> 2;
    int f4  = tid & 3;
    if (dst >= NN) return;
    int start = __ldg(&g_rowstart[dst]);
    int cnt   = __ldg(&g_deg[dst]);
    if (LAYER == 2 && f4 == 0) g_deg[dst] = 0;   // self-restore for next launch
    const __half* hin = (LAYER == 1 ? g_hpreh : g_hpre2h);
    const int4* p4 = (const int4*)(g_csr + start);   // start is 4-aligned
    float4 acc = make_float4(0.f, 0.f, 0.f, 0.f);
    float4 acc2 = acc;
    int n4 = cnt >> 2;
    for (int k = 0; k < n4; k++) {
        int4 e = __ldg(p4 + k);
        float4 v0 = ldh4(hin, e.x, f4);
        float4 v1 = ldh4(hin, e.y, f4);
        float4 v2 = ldh4(hin, e.z, f4);
        float4 v3 = ldh4(hin, e.w, f4);
        acc  = add4(acc,  add4(v0, v1));
        acc2 = add4(acc2, add4(v2, v3));
    }
    const int* ps = g_csr + start;
    for (int i = n4 << 2; i < cnt; i++) {
        int s = __ldg(ps + i);
        acc = add4(acc, ldh4(hin, s, f4));
    }
    acc = add4(acc, acc2);
    // self loop, then scale by dinv[dst], bias, relu
    acc = add4(acc, ldh4(hin, dst, f4));
    float di = g_dinv[dst];
    float h[4];
    h[0] = fmaxf(fmaf(di, acc.x, bs[4 * f4 + 0]), 0.f);
    h[1] = fmaxf(fmaf(di, acc.y, bs[4 * f4 + 1]), 0.f);
    h[2] = fmaxf(fmaf(di, acc.z, bs[4 * f4 + 2]), 0.f);
    h[3] = fmaxf(fmaf(di, acc.w, bs[4 * f4 + 3]), 0.f);

    if (LAYER == 1) {
        // o[4*f4..] = sum_j h_full[j] * W2[j][4*f4..]; gather h_full via group shuffles
        int lane = threadIdx.x & 31;
        int base = lane & ~3;
        unsigned gmask = 0xFu << base;
        float4 o = make_float4(0.f, 0.f, 0.f, 0.f);
#pragma unroll
        for (int l = 0; l < 4; l++) {
#pragma unroll
            for (int m = 0; m < 4; m++) {
                float hv = __shfl_sync(gmask, h[m], base + l, 32);
                o = fma4(hv, w2s4[(4 * l + m) * 4 + f4], o);
            }
        }
        // pre-scale for layer 2: hpre2 = dinv[d] * (h1 @ W2), stored fp16
        o.x *= di; o.y *= di; o.z *= di; o.w *= di;
        sth4(g_hpre2h, dst, f4, o);
    } else {
        int b = is64s ? (int)((const long long*)batch)[dst] : ((const int*)batch)[dst];
        red4(g_pooled + (size_t)b * NH + 4 * f4, make_float4(h[0], h[1], h[2], h[3]));
    }
}

// ---- MLP head (re-zeroes g_pooled after reading) ----
__global__ void k_head(const float* __restrict__ lw1, const float* __restrict__ lb1,
                       const float* __restrict__ lw2, const float* __restrict__ lb2,
                       float* __restrict__ out) {
    __shared__ float w1s[NH * MH];
    __shared__ float w2s[MH * NC];
    __shared__ float b1s[MH];
    __shared__ float b2s[NC];
    for (int i = threadIdx.x; i < NH * MH; i += blockDim.x) w1s[i] = lw1[i];
    for (int i = threadIdx.x; i < MH * NC; i += blockDim.x) w2s[i] = lw2[i];
    if (threadIdx.x < MH) b1s[threadIdx.x] = lb1[threadIdx.x];
    if (threadIdx.x < NC) b2s[threadIdx.x] = lb2[threadIdx.x];
    __syncthreads();
    int g = blockIdx.x * blockDim.x + threadIdx.x;
    if (g >= NG) return;
    float p[NH];
#pragma unroll
    for (int j = 0; j < NH; j++) {
        p[j] = fmaxf(g_pooled[g * NH + j], 0.f);
        g_pooled[g * NH + j] = 0.f;   // self-restore for next launch
    }
    float o[NC];
#pragma unroll
    for (int c = 0; c < NC; c++) o[c] = b2s[c];
    for (int m = 0; m < MH; m++) {
        float hh = b1s[m];
#pragma unroll
        for (int j = 0; j < NH; j++) hh += p[j] * w1s[j * MH + m];
        hh = fmaxf(hh, 0.f);
#pragma unroll
        for (int c = 0; c < NC; c++) o[c] += hh * w2s[m * NC + c];
    }
#pragma unroll
    for (int c = 0; c < NC; c++) out[g * NC + c] = o[c];
}

extern "C" void kernel_launch(void* const* d_in, const int* in_sizes, int n_in,
                              void* d_out, int out_size) {
    const float* x = nullptr;
    const void*  ei = nullptr;
    const void*  batch = nullptr;
    const float *W1 = nullptr, *b1 = nullptr, *W2 = nullptr, *b2 = nullptr;
    const float *lw1 = nullptr, *lb1 = nullptr, *lw2 = nullptr, *lb2 = nullptr;
    for (int i = 0; i < n_in; i++) {
        int sz = in_sizes[i];
        const void* p = d_in[i];
        switch (sz) {
            case NN * NF:   x     = (const float*)p; break;
            case 2 * NE:    ei    = p; break;
            case NN:        batch = p; break;
            case NF * NH:   W1    = (const float*)p; break;
            case NH * NH:   W2    = (const float*)p; break;
            case NH * MH:   lw1   = (const float*)p; break;
            case MH:        lb1   = (const float*)p; break;
            case MH * NC:   lw2   = (const float*)p; break;
            case NC:        lb2   = (const float*)p; break;
            case NH:        if (!b1) b1 = (const float*)p; else b2 = (const float*)p; break;
            default: break;
        }
    }
    float* out = (float*)d_out;

    k_deg<<<FILL4BLK, 256>>>(ei);
    k_scanAgemm<<<2 * NBLK, 256>>>(x, W1);
    k_scanB<<<NBLK, 256>>>();
    k_fill<<<FILL4BLK, 256>>>(ei);
    k_aggfin<1><<<(NN * 4 + 255) / 256, 256>>>(b1, W2, nullptr, nullptr);
    k_aggfin<2><<<(NN * 4 + 255) / 256, 256>>>(b2, nullptr, batch, ei);
    k_head<<<(NG + 255) / 256, 256>>>(lw1, lb1, lw2, lb2, out);
}

// round 17
// speedup vs baseline: 1.0435x; 1.0435x over previous
#include <cuda_runtime.h>
#include <cuda_fp16.h>

#define NN 100000
#define NE 3200000
#define NF 128
#define NH 16
#define MH 100
#define NC 12
#define NG 512
#define NBLK 391        // ceil(NN/256)
#define FILL4BLK 3125   // NE / (256*4)
#define AGGBLK 782      // ceil(NN*2/256)
#define CSRCAP (NE + 3 * NN)   // rowstarts padded to multiples of 4

// ---- device scratch (static, no allocation; 16B-aligned).
// g_deg / g_pooled: zero-init by CUDA, re-zeroed by last reader per launch.
__device__ __align__(16) int            g_csr[CSRCAP];   // src index only
__device__ __align__(16) unsigned short g_pos[NE];       // within-row slot of each edge
__device__ __align__(16) int    g_deg[NN];
__device__ __align__(16) int    g_rowstart[NN];
__device__ __align__(16) int    g_blocksum[512];
__device__ __align__(16) float  g_dinv[NN];
__device__ __align__(16) float  g_hpre[NN * NH];    // x @ W1 (unscaled fp32)
__device__ __align__(16) __half g_hpreh[NN * NH];   // fp16: dinv * (x @ W1)
__device__ __align__(16) __half g_hpre2h[NN * NH];  // fp16: dinv * (h1 @ W2)
__device__ __align__(16) float  g_pooled[NG * NH];

__device__ __forceinline__ void red4(float* p, float4 v) {
    asm volatile("red.global.add.v4.f32 [%0], {%1,%2,%3,%4};"
                 :: "l"(p), "f"(v.x), "f"(v.y), "f"(v.z), "f"(v.w)
                 : "memory");
}
__device__ __forceinline__ float4 fma4(float s, float4 a, float4 acc) {
    acc.x = fmaf(s, a.x, acc.x); acc.y = fmaf(s, a.y, acc.y);
    acc.z = fmaf(s, a.z, acc.z); acc.w = fmaf(s, a.w, acc.w);
    return acc;
}
// gather 8 fp16 features (16B, one transaction) and accumulate into acc[8]
__device__ __forceinline__ void addh8(float* acc, const __half* __restrict__ base,
                                      int node, int f8) {
    uint4 u = __ldg((const uint4*)(base + node * NH + f8 * 8));
    const __half2* hp = (const __half2*)&u;
    float2 f0 = __half22float2(hp[0]);
    float2 f1 = __half22float2(hp[1]);
    float2 f2 = __half22float2(hp[2]);
    float2 f3 = __half22float2(hp[3]);
    acc[0] += f0.x; acc[1] += f0.y; acc[2] += f1.x; acc[3] += f1.y;
    acc[4] += f2.x; acc[5] += f2.y; acc[6] += f3.x; acc[7] += f3.y;
}
// store 8 floats as fp16 (16B)
__device__ __forceinline__ void sth8(__half* __restrict__ base, int node, int f8,
                                     const float* v) {
    uint4 u;
    __half2 a = __floats2half2_rn(v[0], v[1]);
    __half2 b = __floats2half2_rn(v[2], v[3]);
    __half2 c = __floats2half2_rn(v[4], v[5]);
    __half2 d = __floats2half2_rn(v[6], v[7]);
    u.x = *(unsigned*)&a; u.y = *(unsigned*)&b;
    u.z = *(unsigned*)&c; u.w = *(unsigned*)&d;
    *(uint4*)(base + node * NH + f8 * 8) = u;
}
// store float4 as 4 fp16 (8 bytes) — used by scanB conversion
__device__ __forceinline__ void sth4(__half* __restrict__ base, int node, int f4, float4 v) {
    uint2 u;
    __half2 a = __floats2half2_rn(v.x, v.y);
    __half2 b = __floats2half2_rn(v.z, v.w);
    u.x = *(unsigned*)&a;
    u.y = *(unsigned*)&b;
    *(uint2*)(base + node * NH + f4 * 4) = u;
}
// int64 buffers viewed as int32 are [v,0,v,0,...]; sample odd words of the
// EDGE INDEX ONLY (batch_vec is sorted -> leading zeros legitimate there).
__device__ __forceinline__ int probe64(const int* p32) {
    int nz = 0;
#pragma unroll
    for (int k = 1; k < 16; k += 2) nz |= p32[k];
    return nz == 0;
}
// load 4 consecutive edge indices at position e (e % 4 == 0)
__device__ __forceinline__ int4 ld4idx(const void* col, int e, int is64) {
    if (is64) {
        ulonglong2 a = __ldg((const ulonglong2*)((const long long*)col + e));
        ulonglong2 b = __ldg((const ulonglong2*)((const long long*)col + e) + 1);
        return make_int4((int)a.x, (int)a.y, (int)b.x, (int)b.y);
    }
    return __ldg((const int4*)((const int*)col + e));
}

// ---- degree count + per-edge slot record, 4 edges/thread, high occupancy ----
__global__ __launch_bounds__(256) void k_deg(const void* __restrict__ ei) {
    __shared__ int is64s;
    if (threadIdx.x == 0) is64s = probe64((const int*)ei);
    __syncthreads();
    int e = (blockIdx.x * 256 + threadIdx.x) * 4;
    if (e >= NE) return;
    const void* dstcol = is64s ? (const void*)((const long long*)ei + NE)
                               : (const void*)((const int*)ei + NE);
    int4 d = ld4idx(dstcol, e, is64s);
    ushort4 p;
    p.x = (unsigned short)atomicAdd(&g_deg[d.x], 1);
    p.y = (unsigned short)atomicAdd(&g_deg[d.y], 1);
    p.z = (unsigned short)atomicAdd(&g_deg[d.z], 1);
    p.w = (unsigned short)atomicAdd(&g_deg[d.w], 1);
    *(ushort4*)(g_pos + e) = p;
}

// ---- scanA (blocks [0,NBLK)) + gemm1 unscaled fp32 (blocks [NBLK, 2*NBLK)) ----
__global__ __launch_bounds__(256) void k_scanAgemm(const float* __restrict__ x,
                                                   const float* __restrict__ W1) {
    if (blockIdx.x < NBLK) {
        __shared__ int s[256];
        int i = blockIdx.x * 256 + threadIdx.x;
        s[threadIdx.x] = (i < NN) ? ((g_deg[i] + 3) & ~3) : 0;
        __syncthreads();
        for (int o = 128; o > 0; o >>= 1) {
            if (threadIdx.x < o) s[threadIdx.x] += s[threadIdx.x + o];
            __syncthreads();
        }
        if (threadIdx.x == 0) g_blocksum[blockIdx.x] = s[0];
        return;
    }
    __shared__ float4 w4[NF * 4];   // w4[k*4+q] = W1[k][4q..4q+3]
    for (int i = threadIdx.x; i < NF * 4; i += blockDim.x)
        w4[i] = ((const float4*)W1)[i];
    __syncthreads();
    int r = (blockIdx.x - NBLK) * 256 + threadIdx.x;
    if (r >= NN) return;
    float4 a0 = make_float4(0.f, 0.f, 0.f, 0.f);
    float4 a1 = a0, a2 = a0, a3 = a0;
    const float4* xr = (const float4*)(x + (size_t)r * NF);
#pragma unroll 4
    for (int k4 = 0; k4 < NF / 4; k4++) {
        float4 xv = __ldg(xr + k4);
        const float4* wr = &w4[(4 * k4) * 4];
        a0 = fma4(xv.x, wr[0], a0); a1 = fma4(xv.x, wr[1], a1);
        a2 = fma4(xv.x, wr[2], a2); a3 = fma4(xv.x, wr[3], a3);
        a0 = fma4(xv.y, wr[4], a0); a1 = fma4(xv.y, wr[5], a1);
        a2 = fma4(xv.y, wr[6], a2); a3 = fma4(xv.y, wr[7], a3);
        a0 = fma4(xv.z, wr[8], a0); a1 = fma4(xv.z, wr[9], a1);
        a2 = fma4(xv.z, wr[10], a2); a3 = fma4(xv.z, wr[11], a3);
        a0 = fma4(xv.w, wr[12], a0); a1 = fma4(xv.w, wr[13], a1);
        a2 = fma4(xv.w, wr[14], a2); a3 = fma4(xv.w, wr[15], a3);
    }
    float4* o = (float4*)(g_hpre + (size_t)r * NH);
    o[0] = a0; o[1] = a1; o[2] = a2; o[3] = a3;
}

// ---- scanB: block-offset reduction + local scan -> rowstart/dinv;
//      convert hpre fp32 -> scaled fp16 hpreh ----
__global__ void k_scanB() {
    __shared__ int s[256];
    __shared__ int off;
    int t = threadIdx.x;
    int b = blockIdx.x;
    int v = 0;
    if (t < b) v = g_blocksum[t];
    if (t + 256 < b) v += g_blocksum[t + 256];
    s[t] = v;
    __syncthreads();
    for (int o = 128; o > 0; o >>= 1) {
        if (t < o) s[t] += s[t + o];
        __syncthreads();
    }
    if (t == 0) off = s[0];
    __syncthreads();
    int i = b * 256 + t;
    int d  = (i < NN) ? g_deg[i] : 0;
    int d4 = (d + 3) & ~3;
    s[t] = d4;
    __syncthreads();
    for (int o = 1; o < 256; o <<= 1) {
        int vv = (t >= o) ? s[t - o] : 0;
        __syncthreads();
        s[t] += vv;
        __syncthreads();
    }
    if (i < NN) {
        g_rowstart[i] = off + s[t] - d4;
        float di = rsqrtf((float)(d + 1));
        g_dinv[i] = di;
        const float4* hp = (const float4*)(g_hpre + (size_t)i * NH);
        float4 z = make_float4(0.f, 0.f, 0.f, 0.f);
#pragma unroll
        for (int q = 0; q < 4; q++)
            sth4(g_hpreh, i, q, fma4(di, hp[q], z));
    }
}

// ---- CSR fill, standalone, atomic-free, 4 edges/thread, high occupancy ----
__global__ __launch_bounds__(256) void k_fill(const void* __restrict__ ei) {
    __shared__ int is64s;
    if (threadIdx.x == 0) is64s = probe64((const int*)ei);
    __syncthreads();
    int e = (blockIdx.x * 256 + threadIdx.x) * 4;
    if (e >= NE) return;
    const void* dstcol = is64s ? (const void*)((const long long*)ei + NE)
                               : (const void*)((const int*)ei + NE);
    int4 s = ld4idx(ei, e, is64s);
    int4 d = ld4idx(dstcol, e, is64s);
    ushort4 p = *(const ushort4*)(g_pos + e);
    g_csr[__ldg(&g_rowstart[d.x]) + p.x] = s.x;
    g_csr[__ldg(&g_rowstart[d.y]) + p.y] = s.y;
    g_csr[__ldg(&g_rowstart[d.z]) + p.z] = s.z;
    g_csr[__ldg(&g_rowstart[d.w]) + p.w] = s.w;
}

// ---- fused agg+fin, 2 threads per dst (f8 = 8-feature half), 16B fp16 gathers --
// Per edge: 2 transactions (was 4). out_pre = dinv[d]*(sum_N h + h_self)
// LAYER 1: h = relu(out_pre + b1); hpre2h = dinv[d] * (h @ W2)  (2-lane shuffle)
// LAYER 2: v = relu(out_pre + b2); pool via 2x red4; re-zero g_deg
template <int LAYER>
__global__ __launch_bounds__(256) void k_aggfin(const float* __restrict__ bias,
                                                const float* __restrict__ W2,
                                                const void* __restrict__ batch,
                                                const void* __restrict__ ei) {
    __shared__ float w2s[NH * NH];    // row-major W2[j][c]
    __shared__ float bs[NH];
    __shared__ int is64s;
    if (LAYER == 1 && threadIdx.x < NH * NH) w2s[threadIdx.x] = W2[threadIdx.x];
    if (threadIdx.x < NH) bs[threadIdx.x] = bias[threadIdx.x];
    if (LAYER == 2 && threadIdx.x == 0) is64s = probe64((const int*)ei);  // probe EI, not batch
    __syncthreads();

    int tid = blockIdx.x * blockDim.x + threadIdx.x;
    int dst = tid >> 1;
    int f8  = tid & 1;
    if (dst >= NN) return;
    int start = __ldg(&g_rowstart[dst]);
    int cnt   = __ldg(&g_deg[dst]);
    if (LAYER == 2 && f8 == 0) g_deg[dst] = 0;   // self-restore for next launch
    const __half* hin = (LAYER == 1 ? g_hpreh : g_hpre2h);
    const int4* p4 = (const int4*)(g_csr + start);   // start is 4-aligned
    float acc[8];
#pragma unroll
    for (int m = 0; m < 8; m++) acc[m] = 0.f;
    int n4 = cnt >> 2;
    for (int k = 0; k < n4; k++) {
        int4 e = __ldg(p4 + k);
        addh8(acc, hin, e.x, f8);
        addh8(acc, hin, e.y, f8);
        addh8(acc, hin, e.z, f8);
        addh8(acc, hin, e.w, f8);
    }
    const int* ps = g_csr + start;
    for (int i = n4 << 2; i < cnt; i++)
        addh8(acc, hin, __ldg(ps + i), f8);
    // self loop, then scale by dinv[dst], bias, relu
    addh8(acc, hin, dst, f8);
    float di = g_dinv[dst];
    float h[8];
#pragma unroll
    for (int m = 0; m < 8; m++)
        h[m] = fmaxf(fmaf(di, acc[m], bs[8 * f8 + m]), 0.f);

    if (LAYER == 1) {
        // o[c] = sum_j h_full[j] * W2[j][c] for own 8 columns; 2-lane shuffle pair
        int lane = threadIdx.x & 31;
        int base = lane & ~1;
        unsigned gmask = 0x3u << base;
        float o[8];
#pragma unroll
        for (int m = 0; m < 8; m++) o[m] = 0.f;
#pragma unroll
        for (int l = 0; l < 2; l++) {
#pragma unroll
            for (int m = 0; m < 8; m++) {
                float hv = __shfl_sync(gmask, h[m], base + l, 32);
                const float* wrow = &w2s[(l * 8 + m) * NH + f8 * 8];
#pragma unroll
                for (int c = 0; c < 8; c++) o[c] = fmaf(hv, wrow[c], o[c]);
            }
        }
        // pre-scale for layer 2: hpre2 = dinv[d] * (h1 @ W2), stored fp16
#pragma unroll
        for (int c = 0; c < 8; c++) o[c] *= di;
        sth8(g_hpre2h, dst, f8, o);
    } else {
        int b = is64s ? (int)((const long long*)batch)[dst] : ((const int*)batch)[dst];
        float* pool = g_pooled + (size_t)b * NH + 8 * f8;
        red4(pool,     make_float4(h[0], h[1], h[2], h[3]));
        red4(pool + 4, make_float4(h[4], h[5], h[6], h[7]));
    }
}

// ---- MLP head (re-zeroes g_pooled after reading) ----
__global__ void k_head(const float* __restrict__ lw1, const float* __restrict__ lb1,
                       const float* __restrict__ lw2, const float* __restrict__ lb2,
                       float* __restrict__ out) {
    __shared__ float w1s[NH * MH];
    __shared__ float w2s[MH * NC];
    __shared__ float b1s[MH];
    __shared__ float b2s[NC];
    for (int i = threadIdx.x; i < NH * MH; i += blockDim.x) w1s[i] = lw1[i];
    for (int i = threadIdx.x; i < MH * NC; i += blockDim.x) w2s[i] = lw2[i];
    if (threadIdx.x < MH) b1s[threadIdx.x] = lb1[threadIdx.x];
    if (threadIdx.x < NC) b2s[threadIdx.x] = lb2[threadIdx.x];
    __syncthreads();
    int g = blockIdx.x * blockDim.x + threadIdx.x;
    if (g >= NG) return;
    float p[NH];
#pragma unroll
    for (int j = 0; j < NH; j++) {
        p[j] = fmaxf(g_pooled[g * NH + j], 0.f);
        g_pooled[g * NH + j] = 0.f;   // self-restore for next launch
    }
    float o[NC];
#pragma unroll
    for (int c = 0; c < NC; c++) o[c] = b2s[c];
    for (int m = 0; m < MH; m++) {
        float hh = b1s[m];
#pragma unroll
        for (int j = 0; j < NH; j++) hh += p[j] * w1s[j * MH + m];
        hh = fmaxf(hh, 0.f);
#pragma unroll
        for (int c = 0; c < NC; c++) o[c] += hh * w2s[m * NC + c];
    }
#pragma unroll
    for (int c = 0; c < NC; c++) out[g * NC + c] = o[c];
}

extern "C" void kernel_launch(void* const* d_in, const int* in_sizes, int n_in,
                              void* d_out, int out_size) {
    const float* x = nullptr;
    const void*  ei = nullptr;
    const void*  batch = nullptr;
    const float *W1 = nullptr, *b1 = nullptr, *W2 = nullptr, *b2 = nullptr;
    const float *lw1 = nullptr, *lb1 = nullptr, *lw2 = nullptr, *lb2 = nullptr;
    for (int i = 0; i < n_in; i++) {
        int sz = in_sizes[i];
        const void* p = d_in[i];
        switch (sz) {
            case NN * NF:   x     = (const float*)p; break;
            case 2 * NE:    ei    = p; break;
            case NN:        batch = p; break;
            case NF * NH:   W1    = (const float*)p; break;
            case NH * NH:   W2    = (const float*)p; break;
            case NH * MH:   lw1   = (const float*)p; break;
            case MH:        lb1   = (const float*)p; break;
            case MH * NC:   lw2   = (const float*)p; break;
            case NC:        lb2   = (const float*)p; break;
            case NH:        if (!b1) b1 = (const float*)p; else b2 = (const float*)p; break;
            default: break;
        }
    }
    float* out = (float*)d_out;

    k_deg<<<FILL4BLK, 256>>>(ei);
    k_scanAgemm<<<2 * NBLK, 256>>>(x, W1);
    k_scanB<<<NBLK, 256>>>();
    k_fill<<<FILL4BLK, 256>>>(ei);
    k_aggfin<1><<<AGGBLK, 256>>>(b1, W2, nullptr, nullptr);
    k_aggfin<2><<<AGGBLK, 256>>>(b2, nullptr, batch, ei);
    k_head<<<(NG + 255) / 256, 256>>>(lw1, lb1, lw2, lb2, out);
}